// round 2
// baseline (speedup 1.0000x reference)
#include <cuda_runtime.h>
#include <math.h>

#define NNODES 50000
#define NEDGES 800000
#define ETOT   (NEDGES + NNODES)   // reference appends one self-loop per node
#define DIM    256
#define HEADS  8

// ---------------- scratch (static device globals; no allocation) ----------------
__device__ float g_xh[(size_t)NNODES * DIM];     // x @ W for current layer
__device__ float g_h[(size_t)NNODES * DIM];      // layer output (next layer input)
__device__ float g_accum[(size_t)NNODES * DIM];  // raw aggregation sum
__device__ float g_als[NNODES * HEADS];          // per-node src logits
__device__ float g_ald[NNODES * HEADS];          // per-node dst logits
__device__ float g_m[NNODES * HEADS];            // segment max
__device__ float g_denom[NNODES * HEADS];        // segment sum of exp
__device__ float g_ebuf[(size_t)ETOT * HEADS];   // per-edge e, then exp(e-m)

// ---------------- init per layer ----------------
__global__ void init_kernel() {
    int idx = blockIdx.x * blockDim.x + threadIdx.x;
    if (idx < NNODES * DIM) g_accum[idx] = 0.0f;
    if (idx < NNODES * HEADS) {
        g_denom[idx] = 0.0f;
        g_m[idx] = -INFINITY;
    }
}

// ---------------- SGEMM: C[M,256] = A[M,256] @ W[256,256], C = g_xh --------------
// classic 128x128 block tile, BK=8, 256 threads, 8x8 per-thread micro-tile
__global__ void sgemm_kernel(const float* __restrict__ A,
                             const float* __restrict__ B) {
    const int M = NNODES, N = DIM, K = DIM;
    const int BM = 128, BN = 128, BK = 8, TM = 8, TN = 8;
    __shared__ float As[BK][BM];
    __shared__ float Bs[BK][BN];

    int block_row = blockIdx.y;
    int block_col = blockIdx.x;
    int tid = threadIdx.x;

    int tr = tid / (BN / TN);   // 0..15
    int tc = tid % (BN / TN);   // 0..15

    // A loads: each thread loads one float4 (row a_row, cols a_col4..a_col4+3)
    int a_row  = tid >> 1;            // 0..127
    int a_col4 = (tid & 1) * 4;       // 0 or 4
    // B loads: each thread loads one float4
    int b_row  = tid >> 5;            // 0..7
    int b_col4 = (tid & 31) * 4;      // 0..124

    float acc[TM][TN];
#pragma unroll
    for (int i = 0; i < TM; i++)
#pragma unroll
        for (int j = 0; j < TN; j++) acc[i][j] = 0.0f;

    for (int k0 = 0; k0 < K; k0 += BK) {
        int gr = block_row * BM + a_row;
        float4 av = make_float4(0.f, 0.f, 0.f, 0.f);
        if (gr < M) av = *(const float4*)&A[(size_t)gr * K + k0 + a_col4];
        As[a_col4 + 0][a_row] = av.x;
        As[a_col4 + 1][a_row] = av.y;
        As[a_col4 + 2][a_row] = av.z;
        As[a_col4 + 3][a_row] = av.w;

        float4 bv = *(const float4*)&B[(size_t)(k0 + b_row) * N + block_col * BN + b_col4];
        *(float4*)&Bs[b_row][b_col4] = bv;
        __syncthreads();

#pragma unroll
        for (int k = 0; k < BK; k++) {
            float ar[TM], br[TN];
#pragma unroll
            for (int i = 0; i < TM; i++) ar[i] = As[k][tr * TM + i];
#pragma unroll
            for (int j = 0; j < TN; j++) br[j] = Bs[k][tc * TN + j];
#pragma unroll
            for (int i = 0; i < TM; i++)
#pragma unroll
                for (int j = 0; j < TN; j++) acc[i][j] += ar[i] * br[j];
        }
        __syncthreads();
    }

#pragma unroll
    for (int i = 0; i < TM; i++) {
        int gr = block_row * BM + tr * TM + i;
        if (gr < M) {
#pragma unroll
            for (int j = 0; j < TN; j += 4) {
                *(float4*)&g_xh[(size_t)gr * N + block_col * BN + tc * TN + j] =
                    make_float4(acc[i][j], acc[i][j + 1], acc[i][j + 2], acc[i][j + 3]);
            }
        }
    }
}

// ---------------- per-node logits: als[n,h] = <xh[n,h,:], a_src[h,:]> ------------
// one warp per node; lane l covers channels [8l, 8l+8); head = l>>2
__global__ void logits_kernel(const float* __restrict__ a_src,
                              const float* __restrict__ a_dst) {
    int gwarp = (blockIdx.x * blockDim.x + threadIdx.x) >> 5;
    int lane = threadIdx.x & 31;
    if (gwarp >= NNODES) return;

    const float4* xh4 = (const float4*)(g_xh + (size_t)gwarp * DIM);
    float4 v0 = xh4[lane * 2], v1 = xh4[lane * 2 + 1];
    const float4* s4 = (const float4*)a_src;
    const float4* d4 = (const float4*)a_dst;
    float4 s0 = s4[lane * 2], s1 = s4[lane * 2 + 1];
    float4 d0 = d4[lane * 2], d1 = d4[lane * 2 + 1];

    float ps = v0.x * s0.x + v0.y * s0.y + v0.z * s0.z + v0.w * s0.w +
               v1.x * s1.x + v1.y * s1.y + v1.z * s1.z + v1.w * s1.w;
    float pd = v0.x * d0.x + v0.y * d0.y + v0.z * d0.z + v0.w * d0.w +
               v1.x * d1.x + v1.y * d1.y + v1.z * d1.z + v1.w * d1.w;

    ps += __shfl_xor_sync(0xffffffffu, ps, 1);
    ps += __shfl_xor_sync(0xffffffffu, ps, 2);
    pd += __shfl_xor_sync(0xffffffffu, pd, 1);
    pd += __shfl_xor_sync(0xffffffffu, pd, 2);

    if ((lane & 3) == 0) {
        g_als[gwarp * HEADS + (lane >> 2)] = ps;
        g_ald[gwarp * HEADS + (lane >> 2)] = pd;
    }
}

// ---------------- pass A: e = leaky_relu(als[src]+ald[dst]); segment max ---------
__global__ void edge_max_kernel(const int* __restrict__ ei) {
    int idx = blockIdx.x * blockDim.x + threadIdx.x;
    if (idx >= ETOT * HEADS) return;
    int e = idx >> 3, h = idx & 7;
    int s, d;
    if (e < NEDGES) { s = ei[e]; d = ei[NEDGES + e]; }
    else            { s = d = e - NEDGES; }

    float v = g_als[s * HEADS + h] + g_ald[d * HEADS + h];
    v = v > 0.0f ? v : 0.2f * v;
    g_ebuf[idx] = v;

    float* addr = &g_m[d * HEADS + h];
    if (v >= 0.0f) atomicMax((int*)addr, __float_as_int(v));
    else           atomicMin((unsigned int*)addr, (unsigned int)__float_as_int(v));
}

// ---------------- pass B: ex = exp(e - m[dst]); segment sum ----------------------
__global__ void edge_exp_kernel(const int* __restrict__ ei) {
    int idx = blockIdx.x * blockDim.x + threadIdx.x;
    if (idx >= ETOT * HEADS) return;
    int e = idx >> 3, h = idx & 7;
    int d = (e < NEDGES) ? ei[NEDGES + e] : e - NEDGES;

    float ex = expf(g_ebuf[idx] - g_m[d * HEADS + h]);
    g_ebuf[idx] = ex;
    atomicAdd(&g_denom[d * HEADS + h], ex);
}

// ---------------- pass C: accum[dst] += ex * xh[src] (raw, divide later) ---------
// one warp per edge; lane l handles channels [8l, 8l+8); alpha from head l>>2
__global__ void edge_aggr_kernel(const int* __restrict__ ei) {
    int gwarp = (blockIdx.x * blockDim.x + threadIdx.x) >> 5;
    int lane = threadIdx.x & 31;
    if (gwarp >= ETOT) return;
    int s, d;
    if (gwarp < NEDGES) { s = ei[gwarp]; d = ei[NEDGES + gwarp]; }
    else                { s = d = gwarp - NEDGES; }

    float exv = 0.0f;
    if (lane < HEADS) exv = g_ebuf[(size_t)gwarp * HEADS + lane];
    float alpha = __shfl_sync(0xffffffffu, exv, lane >> 2);

    const float4* xs = (const float4*)(g_xh + (size_t)s * DIM) + lane * 2;
    float4 v0 = xs[0], v1 = xs[1];
    float* out = g_accum + (size_t)d * DIM + lane * 8;
    atomicAdd(out + 0, alpha * v0.x);
    atomicAdd(out + 1, alpha * v0.y);
    atomicAdd(out + 2, alpha * v0.z);
    atomicAdd(out + 3, alpha * v0.w);
    atomicAdd(out + 4, alpha * v1.x);
    atomicAdd(out + 5, alpha * v1.y);
    atomicAdd(out + 6, alpha * v1.z);
    atomicAdd(out + 7, alpha * v1.w);
}

// ---------------- finalize: out = accum/denom + b, optional ELU -------------------
__global__ void finalize_kernel(const float* __restrict__ b,
                                float* __restrict__ out, int apply_elu) {
    int idx = blockIdx.x * blockDim.x + threadIdx.x;
    if (idx >= NNODES * DIM) return;
    int c = idx & 255, n = idx >> 8;
    float v = g_accum[idx] / g_denom[n * HEADS + (c >> 5)] + b[c];
    if (apply_elu) v = v > 0.0f ? v : expm1f(v);
    out[idx] = v;
}

// ---------------- host launcher ----------------
extern "C" void kernel_launch(void* const* d_in, const int* in_sizes, int n_in,
                              void* d_out, int out_size) {
    const float* x  = (const float*)d_in[0];
    const int*   ei = (const int*)d_in[1];
    float* out = (float*)d_out;

    void* p_h = nullptr;
    cudaGetSymbolAddress(&p_h, g_h);

    const int TPB = 256;
    dim3 gemm_grid(DIM / 128, (NNODES + 127) / 128);
    int init_blocks  = (NNODES * DIM + TPB - 1) / TPB;
    int log_blocks   = (NNODES * 32 + TPB - 1) / TPB;
    int eh_blocks    = (ETOT * HEADS + TPB - 1) / TPB;
    int aggr_blocks  = ((size_t)ETOT * 32 + TPB - 1) / TPB;
    int fin_blocks   = (NNODES * DIM + TPB - 1) / TPB;

    const float* A = x;
    for (int layer = 0; layer < 4; layer++) {
        const float* W   = (const float*)d_in[2 + 4 * layer];
        const float* as_ = (const float*)d_in[3 + 4 * layer];
        const float* ad_ = (const float*)d_in[4 + 4 * layer];
        const float* b   = (const float*)d_in[5 + 4 * layer];

        init_kernel<<<init_blocks, TPB>>>();
        sgemm_kernel<<<gemm_grid, TPB>>>(A, W);
        logits_kernel<<<log_blocks, TPB>>>(as_, ad_);
        edge_max_kernel<<<eh_blocks, TPB>>>(ei);
        edge_exp_kernel<<<eh_blocks, TPB>>>(ei);
        edge_aggr_kernel<<<aggr_blocks, TPB>>>(ei);

        float* dst = (layer < 3) ? (float*)p_h : out;
        finalize_kernel<<<fin_blocks, TPB>>>(b, dst, layer < 3 ? 1 : 0);
        A = (const float*)p_h;
    }
}

// round 3
// speedup vs baseline: 4.3565x; 4.3565x over previous
#include <cuda_runtime.h>
#include <math.h>

#define NNODES 50000
#define NEDGES 800000
#define ETOT   (NEDGES + NNODES)   // reference appends one self-loop per node
#define DIM    256
#define HEADS  8

// ---------------- scratch (static device globals; no allocation) ----------------
__device__ float g_xh[(size_t)NNODES * DIM];     // x @ W for current layer
__device__ float g_h[(size_t)NNODES * DIM];      // layer output (next layer input)
__device__ float g_als[NNODES * HEADS];          // per-node src logits
__device__ float g_ald[NNODES * HEADS];          // per-node dst logits
// CSR by dst (built once per call; graph is identical across layers)
__device__ int g_deg[NNODES];
__device__ int g_cursor[NNODES];
__device__ int g_off[NNODES + 1];
__device__ int g_csr_src[ETOT];

// ---------------- CSR build ----------------
__global__ void csr_zero_kernel() {
    int i = blockIdx.x * blockDim.x + threadIdx.x;
    if (i < NNODES) { g_deg[i] = 0; g_cursor[i] = 0; }
}

__global__ void csr_count_kernel(const int* __restrict__ ei) {
    int e = blockIdx.x * blockDim.x + threadIdx.x;
    if (e >= ETOT) return;
    int d = (e < NEDGES) ? ei[NEDGES + e] : e - NEDGES;
    atomicAdd(&g_deg[d], 1);
}

// single-block exclusive scan of g_deg -> g_off (50000 elems, 1024 threads)
__global__ void csr_scan_kernel() {
    __shared__ int partial[1024];
    int tid = threadIdx.x;
    const int CH = (NNODES + 1023) / 1024;   // 49
    int base = tid * CH;
    int s = 0;
    for (int i = 0; i < CH; i++) {
        int j = base + i;
        if (j < NNODES) s += g_deg[j];
    }
    partial[tid] = s;
    __syncthreads();
    // Hillis-Steele inclusive scan over partials
    for (int off = 1; off < 1024; off <<= 1) {
        int v = (tid >= off) ? partial[tid - off] : 0;
        __syncthreads();
        partial[tid] += v;
        __syncthreads();
    }
    int run = (tid == 0) ? 0 : partial[tid - 1];
    for (int i = 0; i < CH; i++) {
        int j = base + i;
        if (j < NNODES) {
            int c = g_deg[j];
            g_off[j] = run;
            run += c;
        }
    }
    if (tid == 0) g_off[NNODES] = ETOT;
}

__global__ void csr_scatter_kernel(const int* __restrict__ ei) {
    int e = blockIdx.x * blockDim.x + threadIdx.x;
    if (e >= ETOT) return;
    int s, d;
    if (e < NEDGES) { s = ei[e]; d = ei[NEDGES + e]; }
    else            { s = d = e - NEDGES; }
    int pos = g_off[d] + atomicAdd(&g_cursor[d], 1);
    g_csr_src[pos] = s;
}

// ---------------- SGEMM: g_xh[M,256] = A[M,256] @ W[256,256] --------------------
// 128x128 tile, BK=8, 256 threads, 8x8 micro-tile, double-buffered smem
__global__ void sgemm_kernel(const float* __restrict__ A,
                             const float* __restrict__ B) {
    const int BM = 128, BN = 128, BK = 8;
    __shared__ float As[2][BK][BM];
    __shared__ float Bs[2][BK][BN];

    int tid = threadIdx.x;
    int tr = tid >> 4;          // 0..15
    int tc = tid & 15;          // 0..15
    int a_row  = tid >> 1;      // 0..127
    int a_col4 = (tid & 1) * 4; // 0 or 4
    int b_row  = tid >> 5;      // 0..7
    int b_col4 = (tid & 31) * 4;

    int grow = blockIdx.y * BM + a_row;
    bool aval = grow < NNODES;
    const float* Aptr = A + (size_t)grow * DIM + a_col4;
    const float* Bptr = B + (size_t)b_row * DIM + blockIdx.x * BN + b_col4;

    float acc[8][8];
#pragma unroll
    for (int i = 0; i < 8; i++)
#pragma unroll
        for (int j = 0; j < 8; j++) acc[i][j] = 0.0f;

    float4 av = aval ? *(const float4*)Aptr : make_float4(0.f, 0.f, 0.f, 0.f);
    float4 bv = *(const float4*)Bptr;
    As[0][a_col4 + 0][a_row] = av.x;
    As[0][a_col4 + 1][a_row] = av.y;
    As[0][a_col4 + 2][a_row] = av.z;
    As[0][a_col4 + 3][a_row] = av.w;
    *(float4*)&Bs[0][b_row][b_col4] = bv;
    __syncthreads();

    int cur = 0;
    for (int k0 = BK; k0 < DIM; k0 += BK) {
        av = aval ? *(const float4*)(Aptr + k0) : make_float4(0.f, 0.f, 0.f, 0.f);
        bv = *(const float4*)(Bptr + (size_t)k0 * DIM);

#pragma unroll
        for (int k = 0; k < BK; k++) {
            float ar[8], br[8];
#pragma unroll
            for (int i = 0; i < 8; i++) ar[i] = As[cur][k][tr * 8 + i];
#pragma unroll
            for (int j = 0; j < 8; j++) br[j] = Bs[cur][k][tc * 8 + j];
#pragma unroll
            for (int i = 0; i < 8; i++)
#pragma unroll
                for (int j = 0; j < 8; j++) acc[i][j] += ar[i] * br[j];
        }

        int nxt = cur ^ 1;
        As[nxt][a_col4 + 0][a_row] = av.x;
        As[nxt][a_col4 + 1][a_row] = av.y;
        As[nxt][a_col4 + 2][a_row] = av.z;
        As[nxt][a_col4 + 3][a_row] = av.w;
        *(float4*)&Bs[nxt][b_row][b_col4] = bv;
        __syncthreads();
        cur = nxt;
    }

#pragma unroll
    for (int k = 0; k < BK; k++) {
        float ar[8], br[8];
#pragma unroll
        for (int i = 0; i < 8; i++) ar[i] = As[cur][k][tr * 8 + i];
#pragma unroll
        for (int j = 0; j < 8; j++) br[j] = Bs[cur][k][tc * 8 + j];
#pragma unroll
        for (int i = 0; i < 8; i++)
#pragma unroll
            for (int j = 0; j < 8; j++) acc[i][j] += ar[i] * br[j];
    }

#pragma unroll
    for (int i = 0; i < 8; i++) {
        int gr = blockIdx.y * BM + tr * 8 + i;
        if (gr < NNODES) {
#pragma unroll
            for (int j = 0; j < 8; j += 4) {
                *(float4*)&g_xh[(size_t)gr * DIM + blockIdx.x * BN + tc * 8 + j] =
                    make_float4(acc[i][j], acc[i][j + 1], acc[i][j + 2], acc[i][j + 3]);
            }
        }
    }
}

// ---------------- per-node logits: als[n,h] = <xh[n,h,:], a_src[h,:]> ------------
__global__ void logits_kernel(const float* __restrict__ a_src,
                              const float* __restrict__ a_dst) {
    int gwarp = (blockIdx.x * blockDim.x + threadIdx.x) >> 5;
    int lane = threadIdx.x & 31;
    if (gwarp >= NNODES) return;

    const float4* xh4 = (const float4*)(g_xh + (size_t)gwarp * DIM);
    float4 v0 = xh4[lane * 2], v1 = xh4[lane * 2 + 1];
    const float4* s4 = (const float4*)a_src;
    const float4* d4 = (const float4*)a_dst;
    float4 s0 = s4[lane * 2], s1 = s4[lane * 2 + 1];
    float4 d0 = d4[lane * 2], d1 = d4[lane * 2 + 1];

    float ps = v0.x * s0.x + v0.y * s0.y + v0.z * s0.z + v0.w * s0.w +
               v1.x * s1.x + v1.y * s1.y + v1.z * s1.z + v1.w * s1.w;
    float pd = v0.x * d0.x + v0.y * d0.y + v0.z * d0.z + v0.w * d0.w +
               v1.x * d1.x + v1.y * d1.y + v1.z * d1.z + v1.w * d1.w;

    ps += __shfl_xor_sync(0xffffffffu, ps, 1);
    ps += __shfl_xor_sync(0xffffffffu, ps, 2);
    pd += __shfl_xor_sync(0xffffffffu, pd, 1);
    pd += __shfl_xor_sync(0xffffffffu, pd, 2);

    if ((lane & 3) == 0) {
        g_als[gwarp * HEADS + (lane >> 2)] = ps;
        g_ald[gwarp * HEADS + (lane >> 2)] = pd;
    }
}

// ---------------- fused edge softmax + aggregation (CSR, no atomics) -------------
// one warp per dst node; lane l handles channels [8l,8l+8), head = l>>2
__global__ void aggr_fused_kernel(const float* __restrict__ bvec,
                                  float* __restrict__ out, int apply_elu) {
    int warp = (blockIdx.x * blockDim.x + threadIdx.x) >> 5;
    int lane = threadIdx.x & 31;
    if (warp >= NNODES) return;

    int beg = g_off[warp], end = g_off[warp + 1];
    int h = lane >> 2;
    float aldh = g_ald[warp * HEADS + h];

    // pass 1: per-head max (4 lanes per head compute redundantly)
    float m = -INFINITY;
    for (int i = beg; i < end; i++) {
        int s = g_csr_src[i];
        float e = g_als[s * HEADS + h] + aldh;
        e = e > 0.0f ? e : 0.2f * e;
        m = fmaxf(m, e);
    }

    // pass 2: exp, denom, weighted accumulate
    float denom = 0.0f;
    float acc[8];
#pragma unroll
    for (int j = 0; j < 8; j++) acc[j] = 0.0f;

    for (int i = beg; i < end; i++) {
        int s = g_csr_src[i];
        float e = g_als[s * HEADS + h] + aldh;
        e = e > 0.0f ? e : 0.2f * e;
        float a = expf(e - m);
        denom += a;
        const float4* xs = (const float4*)(g_xh + (size_t)s * DIM) + lane * 2;
        float4 v0 = xs[0], v1 = xs[1];
        acc[0] += a * v0.x; acc[1] += a * v0.y;
        acc[2] += a * v0.z; acc[3] += a * v0.w;
        acc[4] += a * v1.x; acc[5] += a * v1.y;
        acc[6] += a * v1.z; acc[7] += a * v1.w;
    }

    float inv = 1.0f / denom;
    float* o = out + (size_t)warp * DIM + lane * 8;
    const float* bb = bvec + lane * 8;
#pragma unroll
    for (int j = 0; j < 8; j++) {
        float v = acc[j] * inv + bb[j];
        if (apply_elu) v = v > 0.0f ? v : expm1f(v);
        o[j] = v;
    }
}

// ---------------- host launcher ----------------
extern "C" void kernel_launch(void* const* d_in, const int* in_sizes, int n_in,
                              void* d_out, int out_size) {
    const float* x  = (const float*)d_in[0];
    const int*   ei = (const int*)d_in[1];
    float* out = (float*)d_out;

    void* p_h = nullptr;
    cudaGetSymbolAddress(&p_h, g_h);

    const int TPB = 256;
    dim3 gemm_grid(DIM / 128, (NNODES + 127) / 128);
    int node_blocks = (NNODES + TPB - 1) / TPB;
    int edge_blocks = (ETOT + TPB - 1) / TPB;
    int warp_blocks = (NNODES * 32 + TPB - 1) / TPB;   // one warp per node

    // build CSR once (same graph for all 4 layers)
    csr_zero_kernel<<<node_blocks, TPB>>>();
    csr_count_kernel<<<edge_blocks, TPB>>>(ei);
    csr_scan_kernel<<<1, 1024>>>();
    csr_scatter_kernel<<<edge_blocks, TPB>>>(ei);

    const float* A = x;
    for (int layer = 0; layer < 4; layer++) {
        const float* W   = (const float*)d_in[2 + 4 * layer];
        const float* as_ = (const float*)d_in[3 + 4 * layer];
        const float* ad_ = (const float*)d_in[4 + 4 * layer];
        const float* b   = (const float*)d_in[5 + 4 * layer];

        sgemm_kernel<<<gemm_grid, TPB>>>(A, W);
        logits_kernel<<<warp_blocks, TPB>>>(as_, ad_);

        float* dst = (layer < 3) ? (float*)p_h : out;
        aggr_fused_kernel<<<warp_blocks, TPB>>>(b, dst, layer < 3 ? 1 : 0);
        A = (const float*)p_h;
    }
}

// round 4
// speedup vs baseline: 5.9573x; 1.3675x over previous
#include <cuda_runtime.h>
#include <cuda_bf16.h>
#include <math.h>
#include <stdint.h>

#define NNODES 50000
#define NEDGES 800000
#define ETOT   (NEDGES + NNODES)   // reference appends one self-loop per node
#define DIM    256
#define HEADS  8

// ---------------- scratch (static device globals; no allocation) ----------------
__device__ float g_xh[(size_t)NNODES * DIM];     // x @ W for current layer
__device__ float g_h[(size_t)NNODES * DIM];      // layer output (next layer input)
__device__ float g_als[NNODES * HEADS];          // per-node src logits
__device__ float g_ald[NNODES * HEADS];          // per-node dst logits
__device__ __nv_bfloat16 g_wt_hi[DIM * DIM];     // W^T split high part  [n][k]
__device__ __nv_bfloat16 g_wt_lo[DIM * DIM];     // W^T split low part   [n][k]
// CSR by dst (built once per call; graph identical across layers)
__device__ int g_deg[NNODES];
__device__ int g_cursor[NNODES];
__device__ int g_off[NNODES + 1];
__device__ int g_csr_src[ETOT];

// ---------------- CSR build ----------------
__global__ void csr_zero_kernel() {
    int i = blockIdx.x * blockDim.x + threadIdx.x;
    if (i < NNODES) { g_deg[i] = 0; g_cursor[i] = 0; }
}

__global__ void csr_count_kernel(const int* __restrict__ ei) {
    int e = blockIdx.x * blockDim.x + threadIdx.x;
    if (e >= ETOT) return;
    int d = (e < NEDGES) ? ei[NEDGES + e] : e - NEDGES;
    atomicAdd(&g_deg[d], 1);
}

// single-block exclusive scan of g_deg -> g_off
__global__ void csr_scan_kernel() {
    __shared__ int partial[1024];
    int tid = threadIdx.x;
    const int CH = (NNODES + 1023) / 1024;
    int base = tid * CH;
    int s = 0;
    for (int i = 0; i < CH; i++) {
        int j = base + i;
        if (j < NNODES) s += g_deg[j];
    }
    partial[tid] = s;
    __syncthreads();
    for (int off = 1; off < 1024; off <<= 1) {
        int v = (tid >= off) ? partial[tid - off] : 0;
        __syncthreads();
        partial[tid] += v;
        __syncthreads();
    }
    int run = (tid == 0) ? 0 : partial[tid - 1];
    for (int i = 0; i < CH; i++) {
        int j = base + i;
        if (j < NNODES) {
            int c = g_deg[j];
            g_off[j] = run;
            run += c;
        }
    }
    if (tid == 0) g_off[NNODES] = ETOT;
}

__global__ void csr_scatter_kernel(const int* __restrict__ ei) {
    int e = blockIdx.x * blockDim.x + threadIdx.x;
    if (e >= ETOT) return;
    int s, d;
    if (e < NEDGES) { s = ei[e]; d = ei[NEDGES + e]; }
    else            { s = d = e - NEDGES; }
    int pos = g_off[d] + atomicAdd(&g_cursor[d], 1);
    g_csr_src[pos] = s;
}

// ---------------- W transform: Wt_hi/lo[n][k] = split(W[k][n]) ----------------
__global__ void wsplit_kernel(const float* __restrict__ W) {
    int idx = blockIdx.x * blockDim.x + threadIdx.x;  // 65536
    int k = idx >> 8, n = idx & 255;                   // coalesced read of W[k][:]
    float v = W[k * DIM + n];
    __nv_bfloat16 hi = __float2bfloat16(v);
    float r = v - __bfloat162float(hi);
    g_wt_hi[n * DIM + k] = hi;
    g_wt_lo[n * DIM + k] = __float2bfloat16(r);
}

// ---------------- tensor-core GEMM: g_xh = A @ W via bf16x3 ----------------
__device__ __forceinline__ void ldsm4(uint32_t* r, uint32_t addr) {
    asm volatile("ldmatrix.sync.aligned.m8n8.x4.shared.b16 {%0,%1,%2,%3}, [%4];"
                 : "=r"(r[0]), "=r"(r[1]), "=r"(r[2]), "=r"(r[3]) : "r"(addr));
}

__device__ __forceinline__ void mma16816(float* c, const uint32_t* a, const uint32_t* b) {
    asm volatile("mma.sync.aligned.m16n8k16.row.col.f32.bf16.bf16.f32 "
                 "{%0,%1,%2,%3}, {%4,%5,%6,%7}, {%8,%9}, {%0,%1,%2,%3};"
                 : "+f"(c[0]), "+f"(c[1]), "+f"(c[2]), "+f"(c[3])
                 : "r"(a[0]), "r"(a[1]), "r"(a[2]), "r"(a[3]), "r"(b[0]), "r"(b[1]));
}

__device__ __forceinline__ void split_store4(float4 v, __nv_bfloat16* hi, __nv_bfloat16* lo) {
    __nv_bfloat16 h0 = __float2bfloat16(v.x);
    __nv_bfloat16 h1 = __float2bfloat16(v.y);
    __nv_bfloat16 h2 = __float2bfloat16(v.z);
    __nv_bfloat16 h3 = __float2bfloat16(v.w);
    __nv_bfloat162* H = (__nv_bfloat162*)hi;
    H[0] = __halves2bfloat162(h0, h1);
    H[1] = __halves2bfloat162(h2, h3);
    __nv_bfloat162* L = (__nv_bfloat162*)lo;
    L[0] = __halves2bfloat162(__float2bfloat16(v.x - __bfloat162float(h0)),
                              __float2bfloat16(v.y - __bfloat162float(h1)));
    L[1] = __halves2bfloat162(__float2bfloat16(v.z - __bfloat162float(h2)),
                              __float2bfloat16(v.w - __bfloat162float(h3)));
}

// CTA tile 128x128, BK=16, 8 warps (warp tile 32m x 64n), double-buffered smem.
// smem row pitch = 24 bf16 (48B) -> conflict-free ldmatrix phases.
__global__ __launch_bounds__(256) void mma_gemm_kernel(const float* __restrict__ A) {
    __shared__ __nv_bfloat16 sA[2][2][128 * 24];   // [buf][hi/lo][m*24 + k]
    __shared__ __nv_bfloat16 sB[2][2][128 * 24];   // [buf][hi/lo][n*24 + k]

    const int tid = threadIdx.x;
    const int lane = tid & 31;
    const int wid = tid >> 5;
    const int warpM = wid & 3;   // 4 warps over M (32 rows each)
    const int warpN = wid >> 2;  // 2 warps over N (64 cols each)
    const int bm = blockIdx.y, bn = blockIdx.x;

    // A staging: thread loads 2 float4s (loadIdx = tid*2 + j)
    const int l0 = tid * 2, l1 = tid * 2 + 1;
    const int ar0 = l0 >> 2, ak0 = (l0 & 3) * 4;
    const int ar1 = l1 >> 2, ak1 = (l1 & 3) * 4;
    const size_t grow0 = (size_t)bm * 128 + ar0;
    const size_t grow1 = (size_t)bm * 128 + ar1;
    const bool av0 = grow0 < NNODES, av1 = grow1 < NNODES;
    const float* Ap0 = A + grow0 * DIM + ak0;
    const float* Ap1 = A + grow1 * DIM + ak1;

    // B staging: threads 0-127 load hi rows, 128-255 lo rows (each 16 bf16)
    const int brow = tid & 127;
    const __nv_bfloat16* Bsrc =
        ((tid < 128) ? g_wt_hi : g_wt_lo) + (size_t)(bn * 128 + brow) * DIM;
    const int bsel = (tid < 128) ? 0 : 1;

    float c[2][8][4];
#pragma unroll
    for (int i = 0; i < 2; i++)
#pragma unroll
        for (int j = 0; j < 8; j++)
#pragma unroll
            for (int q = 0; q < 4; q++) c[i][j][q] = 0.0f;

    uint32_t aBase[2][2], bBase[2][2];
#pragma unroll
    for (int b_ = 0; b_ < 2; b_++)
#pragma unroll
        for (int s_ = 0; s_ < 2; s_++) {
            aBase[b_][s_] = (uint32_t)__cvta_generic_to_shared(&sA[b_][s_][0]);
            bBase[b_][s_] = (uint32_t)__cvta_generic_to_shared(&sB[b_][s_][0]);
        }

    const float4 f40 = make_float4(0.f, 0.f, 0.f, 0.f);
    float4 a0r, a1r;
    uint4 b0r, b1r;

#define STAGE_LOAD(K0)                                          \
    do {                                                        \
        a0r = av0 ? *(const float4*)(Ap0 + (K0)) : f40;         \
        a1r = av1 ? *(const float4*)(Ap1 + (K0)) : f40;         \
        b0r = *(const uint4*)(Bsrc + (K0));                     \
        b1r = *(const uint4*)(Bsrc + (K0) + 8);                 \
    } while (0)

#define STAGE_STORE(B_)                                                    \
    do {                                                                   \
        split_store4(a0r, &sA[B_][0][ar0 * 24 + ak0], &sA[B_][1][ar0 * 24 + ak0]); \
        split_store4(a1r, &sA[B_][0][ar1 * 24 + ak1], &sA[B_][1][ar1 * 24 + ak1]); \
        *(uint4*)&sB[B_][bsel][brow * 24 + 0] = b0r;                       \
        *(uint4*)&sB[B_][bsel][brow * 24 + 8] = b1r;                       \
    } while (0)

    STAGE_LOAD(0);
    STAGE_STORE(0);
    __syncthreads();

    const uint32_t aoff = (uint32_t)((warpM * 32 + (lane & 15)) * 48 + ((lane >> 4) << 4));
    const uint32_t boff = (uint32_t)((warpN * 64 + ((lane >> 4) & 1) * 8 + (lane & 7)) * 48 +
                                     (((lane >> 3) & 1) << 4));

    int buf = 0;
    for (int kc = 0; kc < 16; kc++) {
        if (kc < 15) STAGE_LOAD((kc + 1) * 16);

        uint32_t ah[2][4], alr[2][4], bh[8][2], blr[8][2];
        ldsm4(ah[0], aBase[buf][0] + aoff);
        ldsm4(ah[1], aBase[buf][0] + aoff + 16 * 48);
        ldsm4(alr[0], aBase[buf][1] + aoff);
        ldsm4(alr[1], aBase[buf][1] + aoff + 16 * 48);
#pragma unroll
        for (int p = 0; p < 4; p++) {
            ldsm4(&bh[2 * p][0], bBase[buf][0] + boff + p * 16 * 48);
            ldsm4(&blr[2 * p][0], bBase[buf][1] + boff + p * 16 * 48);
        }

#pragma unroll
        for (int tm = 0; tm < 2; tm++)
#pragma unroll
            for (int tn = 0; tn < 8; tn++) {
                mma16816(c[tm][tn], ah[tm], bh[tn]);   // hi*hi
                mma16816(c[tm][tn], ah[tm], blr[tn]);  // hi*lo
                mma16816(c[tm][tn], alr[tm], bh[tn]);  // lo*hi
            }

        if (kc < 15) {
            STAGE_STORE(buf ^ 1);
            __syncthreads();
            buf ^= 1;
        }
    }

    // epilogue
    const int g = lane >> 2, cc = (lane & 3) * 2;
#pragma unroll
    for (int tm = 0; tm < 2; tm++) {
        int r0 = bm * 128 + warpM * 32 + tm * 16 + g;
        int r1 = r0 + 8;
#pragma unroll
        for (int tn = 0; tn < 8; tn++) {
            int col = bn * 128 + warpN * 64 + tn * 8 + cc;
            if (r0 < NNODES)
                *(float2*)&g_xh[(size_t)r0 * DIM + col] = make_float2(c[tm][tn][0], c[tm][tn][1]);
            if (r1 < NNODES)
                *(float2*)&g_xh[(size_t)r1 * DIM + col] = make_float2(c[tm][tn][2], c[tm][tn][3]);
        }
    }
#undef STAGE_LOAD
#undef STAGE_STORE
}

// ---------------- per-node logits: als[n,h] = <xh[n,h,:], a_src[h,:]> ------------
__global__ void logits_kernel(const float* __restrict__ a_src,
                              const float* __restrict__ a_dst) {
    int gwarp = (blockIdx.x * blockDim.x + threadIdx.x) >> 5;
    int lane = threadIdx.x & 31;
    if (gwarp >= NNODES) return;

    const float4* xh4 = (const float4*)(g_xh + (size_t)gwarp * DIM);
    float4 v0 = xh4[lane * 2], v1 = xh4[lane * 2 + 1];
    const float4* s4 = (const float4*)a_src;
    const float4* d4 = (const float4*)a_dst;
    float4 s0 = s4[lane * 2], s1 = s4[lane * 2 + 1];
    float4 d0 = d4[lane * 2], d1 = d4[lane * 2 + 1];

    float ps = v0.x * s0.x + v0.y * s0.y + v0.z * s0.z + v0.w * s0.w +
               v1.x * s1.x + v1.y * s1.y + v1.z * s1.z + v1.w * s1.w;
    float pd = v0.x * d0.x + v0.y * d0.y + v0.z * d0.z + v0.w * d0.w +
               v1.x * d1.x + v1.y * d1.y + v1.z * d1.z + v1.w * d1.w;

    ps += __shfl_xor_sync(0xffffffffu, ps, 1);
    ps += __shfl_xor_sync(0xffffffffu, ps, 2);
    pd += __shfl_xor_sync(0xffffffffu, pd, 1);
    pd += __shfl_xor_sync(0xffffffffu, pd, 2);

    if ((lane & 3) == 0) {
        g_als[gwarp * HEADS + (lane >> 2)] = ps;
        g_ald[gwarp * HEADS + (lane >> 2)] = pd;
    }
}

// ---------------- fused edge online-softmax + aggregation (CSR) -----------------
// one warp per dst node; lane l handles channels [8l,8l+8), head = l>>2
__global__ void aggr_fused_kernel(const float* __restrict__ bvec,
                                  float* __restrict__ out, int apply_elu) {
    int warp = (blockIdx.x * blockDim.x + threadIdx.x) >> 5;
    int lane = threadIdx.x & 31;
    if (warp >= NNODES) return;

    int beg = g_off[warp], end = g_off[warp + 1];
    int h = lane >> 2;
    float aldh = g_ald[warp * HEADS + h];

    float m = -INFINITY, denom = 0.0f;
    float acc[8];
#pragma unroll
    for (int j = 0; j < 8; j++) acc[j] = 0.0f;

    for (int i = beg; i < end; i++) {
        int s = g_csr_src[i];
        float e = g_als[s * HEADS + h] + aldh;
        e = e > 0.0f ? e : 0.2f * e;
        float a;
        if (e > m) {
            float r = expf(m - e);   // first iteration: exp(-inf) = 0
            denom *= r;
#pragma unroll
            for (int j = 0; j < 8; j++) acc[j] *= r;
            m = e;
            a = 1.0f;
        } else {
            a = expf(e - m);
        }
        denom += a;
        const float4* xs = (const float4*)(g_xh + (size_t)s * DIM) + lane * 2;
        float4 v0 = xs[0], v1 = xs[1];
        acc[0] += a * v0.x; acc[1] += a * v0.y;
        acc[2] += a * v0.z; acc[3] += a * v0.w;
        acc[4] += a * v1.x; acc[5] += a * v1.y;
        acc[6] += a * v1.z; acc[7] += a * v1.w;
    }

    float inv = 1.0f / denom;
    float* o = out + (size_t)warp * DIM + lane * 8;
    const float* bb = bvec + lane * 8;
#pragma unroll
    for (int j = 0; j < 8; j++) {
        float v = acc[j] * inv + bb[j];
        if (apply_elu) v = v > 0.0f ? v : expm1f(v);
        o[j] = v;
    }
}

// ---------------- host launcher ----------------
extern "C" void kernel_launch(void* const* d_in, const int* in_sizes, int n_in,
                              void* d_out, int out_size) {
    const float* x  = (const float*)d_in[0];
    const int*   ei = (const int*)d_in[1];
    float* out = (float*)d_out;

    void* p_h = nullptr;
    cudaGetSymbolAddress(&p_h, g_h);

    const int TPB = 256;
    dim3 gemm_grid(DIM / 128, (NNODES + 127) / 128);
    int node_blocks = (NNODES + TPB - 1) / TPB;
    int edge_blocks = (ETOT + TPB - 1) / TPB;
    int warp_blocks = (NNODES * 32 + TPB - 1) / TPB;   // one warp per node
    int wsplit_blocks = (DIM * DIM) / TPB;

    // build CSR once (same graph for all 4 layers)
    csr_zero_kernel<<<node_blocks, TPB>>>();
    csr_count_kernel<<<edge_blocks, TPB>>>(ei);
    csr_scan_kernel<<<1, 1024>>>();
    csr_scatter_kernel<<<edge_blocks, TPB>>>(ei);

    const float* A = x;
    for (int layer = 0; layer < 4; layer++) {
        const float* W   = (const float*)d_in[2 + 4 * layer];
        const float* as_ = (const float*)d_in[3 + 4 * layer];
        const float* ad_ = (const float*)d_in[4 + 4 * layer];
        const float* b   = (const float*)d_in[5 + 4 * layer];

        wsplit_kernel<<<wsplit_blocks, TPB>>>(W);
        mma_gemm_kernel<<<gemm_grid, TPB>>>(A);
        logits_kernel<<<warp_blocks, TPB>>>(as_, ad_);

        float* dst = (layer < 3) ? (float*)p_h : out;
        aggr_fused_kernel<<<warp_blocks, TPB>>>(b, dst, layer < 3 ? 1 : 0);
        A = (const float*)p_h;
    }
}

// round 6
// speedup vs baseline: 6.8845x; 1.1556x over previous
#include <cuda_runtime.h>
#include <cuda_bf16.h>
#include <math.h>
#include <stdint.h>

#define NNODES 50000
#define NEDGES 800000
#define ETOT   (NEDGES + NNODES)   // reference appends one self-loop per node
#define DIM    256
#define HEADS  8

// ---------------- scratch (static device globals; no allocation) ----------------
__device__ float g_xh[(size_t)NNODES * DIM];             // x @ W (fp32)
__device__ __nv_bfloat16 g_in_hi[(size_t)NNODES * DIM];  // layer input split hi
__device__ __nv_bfloat16 g_in_lo[(size_t)NNODES * DIM];  // layer input split lo
__device__ float g_als[NNODES * HEADS];
__device__ float g_ald[NNODES * HEADS];
__device__ __nv_bfloat16 g_wt_hi[DIM * DIM];             // W^T split hi [n][k]
__device__ __nv_bfloat16 g_wt_lo[DIM * DIM];             // W^T split lo [n][k]
// CSR by dst
__device__ int g_deg[NNODES];
__device__ int g_cursor[NNODES];
__device__ int g_off[NNODES + 1];
__device__ int g_csr_src[ETOT];

// ---------------- CSR build ----------------
__global__ void csr_zero_kernel() {
    int i = blockIdx.x * blockDim.x + threadIdx.x;
    if (i < NNODES) { g_deg[i] = 0; g_cursor[i] = 0; }
}

__global__ void csr_count_kernel(const int* __restrict__ ei) {
    int e = blockIdx.x * blockDim.x + threadIdx.x;
    if (e >= ETOT) return;
    int d = (e < NEDGES) ? ei[NEDGES + e] : e - NEDGES;
    atomicAdd(&g_deg[d], 1);
}

__global__ void csr_scan_kernel() {
    __shared__ int partial[1024];
    int tid = threadIdx.x;
    const int CH = (NNODES + 1023) / 1024;
    int base = tid * CH;
    int s = 0;
    for (int i = 0; i < CH; i++) {
        int j = base + i;
        if (j < NNODES) s += g_deg[j];
    }
    partial[tid] = s;
    __syncthreads();
    for (int off = 1; off < 1024; off <<= 1) {
        int v = (tid >= off) ? partial[tid - off] : 0;
        __syncthreads();
        partial[tid] += v;
        __syncthreads();
    }
    int run = (tid == 0) ? 0 : partial[tid - 1];
    for (int i = 0; i < CH; i++) {
        int j = base + i;
        if (j < NNODES) {
            int c = g_deg[j];
            g_off[j] = run;
            run += c;
        }
    }
    if (tid == 0) g_off[NNODES] = ETOT;
}

__global__ void csr_scatter_kernel(const int* __restrict__ ei) {
    int e = blockIdx.x * blockDim.x + threadIdx.x;
    if (e >= ETOT) return;
    int s, d;
    if (e < NEDGES) { s = ei[e]; d = ei[NEDGES + e]; }
    else            { s = d = e - NEDGES; }
    int pos = g_off[d] + atomicAdd(&g_cursor[d], 1);
    g_csr_src[pos] = s;
}

// ---------------- splits ----------------
__global__ void wsplit_kernel(const float* __restrict__ W) {
    int idx = blockIdx.x * blockDim.x + threadIdx.x;  // 65536
    int k = idx >> 8, n = idx & 255;
    float v = W[k * DIM + n];
    __nv_bfloat16 hi = __float2bfloat16(v);
    g_wt_hi[n * DIM + k] = hi;
    g_wt_lo[n * DIM + k] = __float2bfloat16(v - __bfloat162float(hi));
}

__global__ void xsplit_kernel(const float* __restrict__ x) {
    int idx = blockIdx.x * blockDim.x + threadIdx.x;   // per 4 elems
    if (idx >= NNODES * DIM / 4) return;
    float4 v = ((const float4*)x)[idx];
    __nv_bfloat16 h0 = __float2bfloat16(v.x), h1 = __float2bfloat16(v.y);
    __nv_bfloat16 h2 = __float2bfloat16(v.z), h3 = __float2bfloat16(v.w);
    __nv_bfloat162* H = (__nv_bfloat162*)g_in_hi + idx * 2;
    H[0] = __halves2bfloat162(h0, h1);
    H[1] = __halves2bfloat162(h2, h3);
    __nv_bfloat162* L = (__nv_bfloat162*)g_in_lo + idx * 2;
    L[0] = __halves2bfloat162(__float2bfloat16(v.x - __bfloat162float(h0)),
                              __float2bfloat16(v.y - __bfloat162float(h1)));
    L[1] = __halves2bfloat162(__float2bfloat16(v.z - __bfloat162float(h2)),
                              __float2bfloat16(v.w - __bfloat162float(h3)));
}

// ---------------- tensor-core GEMM: g_xh = (Ahi+Alo) @ (Bhi+Blo)^T via mma.sync --
__device__ __forceinline__ void ldsm4(uint32_t* r, uint32_t addr) {
    asm volatile("ldmatrix.sync.aligned.m8n8.x4.shared.b16 {%0,%1,%2,%3}, [%4];"
                 : "=r"(r[0]), "=r"(r[1]), "=r"(r[2]), "=r"(r[3]) : "r"(addr));
}

__device__ __forceinline__ void mma16816(float* c, const uint32_t* a, const uint32_t* b) {
    asm volatile("mma.sync.aligned.m16n8k16.row.col.f32.bf16.bf16.f32 "
                 "{%0,%1,%2,%3}, {%4,%5,%6,%7}, {%8,%9}, {%0,%1,%2,%3};"
                 : "+f"(c[0]), "+f"(c[1]), "+f"(c[2]), "+f"(c[3])
                 : "r"(a[0]), "r"(a[1]), "r"(a[2]), "r"(a[3]), "r"(b[0]), "r"(b[1]));
}

#define CPA16(dst, src, n) \
    asm volatile("cp.async.cg.shared.global [%0], [%1], 16, %2;" \
                 :: "r"(dst), "l"(src), "r"(n))

// smem: A tiles [buf][hi/lo] @ (buf*2+s)*6144, B tiles @ 24576 + (buf*2+s)*6144
// each tile: 128 rows x 16 bf16, row pitch 48B (conflict-free ldmatrix phases)
#define TILE_B   6144
#define B_REGION 24576
#define GEMM_SMEM 49152

__global__ __launch_bounds__(256) void mma_gemm_kernel() {
    extern __shared__ char smem[];
    uint32_t sb;
    asm("{ .reg .u64 t; cvta.to.shared.u64 t, %1; cvt.u32.u64 %0, t; }"
        : "=r"(sb) : "l"(smem));

    const int tid = threadIdx.x, lane = tid & 31, wid = tid >> 5;
    const int warpM = wid & 3, warpN = wid >> 2;
    const int bm = blockIdx.y, bn = blockIdx.x;

    // staging: thread -> one 16B chunk per tile per stage
    const int srow = tid >> 1, shalf = tid & 1;
    const uint32_t sdst = (uint32_t)(srow * 48 + shalf * 16);
    int grA = bm * 128 + srow;
    const uint32_t aok = (grA < NNODES) ? 16u : 0u;
    if (grA >= NNODES) grA = 0;   // keep address in-bounds; src-size=0 zero-fills
    const char* pAh = (const char*)(g_in_hi + (size_t)grA * DIM + shalf * 8);
    const char* pAl = (const char*)(g_in_lo + (size_t)grA * DIM + shalf * 8);
    const char* pBh = (const char*)(g_wt_hi + (size_t)(bn * 128 + srow) * DIM + shalf * 8);
    const char* pBl = (const char*)(g_wt_lo + (size_t)(bn * 128 + srow) * DIM + shalf * 8);

    float c[2][8][4];
#pragma unroll
    for (int i = 0; i < 2; i++)
#pragma unroll
        for (int j = 0; j < 8; j++)
#pragma unroll
            for (int q = 0; q < 4; q++) c[i][j][q] = 0.0f;

#define ISSUE(BUF, KB)                                                   \
    do {                                                                 \
        CPA16(sb + ((BUF)*2 + 0) * TILE_B + sdst, pAh + (KB), aok);      \
        CPA16(sb + ((BUF)*2 + 1) * TILE_B + sdst, pAl + (KB), aok);      \
        CPA16(sb + B_REGION + ((BUF)*2 + 0) * TILE_B + sdst, pBh + (KB), 16u); \
        CPA16(sb + B_REGION + ((BUF)*2 + 1) * TILE_B + sdst, pBl + (KB), 16u); \
        asm volatile("cp.async.commit_group;" ::: "memory");             \
    } while (0)

    const uint32_t aoff = (uint32_t)((warpM * 32 + (lane & 15)) * 48 + ((lane >> 4) << 4));
    const uint32_t boff = (uint32_t)((warpN * 64 + ((lane >> 4) & 1) * 8 + (lane & 7)) * 48 +
                                     (((lane >> 3) & 1) << 4));

    ISSUE(0, 0);

    int buf = 0;
    for (int kc = 0; kc < 16; kc++) {
        asm volatile("cp.async.wait_group 0;" ::: "memory");  // stage kc landed
        __syncthreads();   // visibility + all reads of buf^1 (iter kc-1) finished
        if (kc < 15) ISSUE(buf ^ 1, (kc + 1) * 32);           // overlaps compute below

        const uint32_t aH = sb + (buf * 2 + 0) * TILE_B;
        const uint32_t aL = sb + (buf * 2 + 1) * TILE_B;
        const uint32_t bH = sb + B_REGION + (buf * 2 + 0) * TILE_B;
        const uint32_t bL = sb + B_REGION + (buf * 2 + 1) * TILE_B;

        uint32_t ah[2][4], alr[2][4], bh[8][2], blr[8][2];
        ldsm4(ah[0], aH + aoff);
        ldsm4(ah[1], aH + aoff + 16 * 48);
        ldsm4(alr[0], aL + aoff);
        ldsm4(alr[1], aL + aoff + 16 * 48);
#pragma unroll
        for (int p = 0; p < 4; p++) {
            ldsm4(&bh[2 * p][0], bH + boff + p * 16 * 48);
            ldsm4(&blr[2 * p][0], bL + boff + p * 16 * 48);
        }

#pragma unroll
        for (int tm = 0; tm < 2; tm++)
#pragma unroll
            for (int tn = 0; tn < 8; tn++) {
                mma16816(c[tm][tn], ah[tm], bh[tn]);   // hi*hi
                mma16816(c[tm][tn], ah[tm], blr[tn]);  // hi*lo
                mma16816(c[tm][tn], alr[tm], bh[tn]);  // lo*hi
            }
        buf ^= 1;
    }

    // epilogue
    const int g = lane >> 2, cc = (lane & 3) * 2;
#pragma unroll
    for (int tm = 0; tm < 2; tm++) {
        int r0 = bm * 128 + warpM * 32 + tm * 16 + g;
        int r1 = r0 + 8;
#pragma unroll
        for (int tn = 0; tn < 8; tn++) {
            int col = bn * 128 + warpN * 64 + tn * 8 + cc;
            if (r0 < NNODES)
                *(float2*)&g_xh[(size_t)r0 * DIM + col] = make_float2(c[tm][tn][0], c[tm][tn][1]);
            if (r1 < NNODES)
                *(float2*)&g_xh[(size_t)r1 * DIM + col] = make_float2(c[tm][tn][2], c[tm][tn][3]);
        }
    }
#undef ISSUE
}

// ---------------- per-node logits ----------------
__global__ void logits_kernel(const float* __restrict__ a_src,
                              const float* __restrict__ a_dst) {
    int gwarp = (blockIdx.x * blockDim.x + threadIdx.x) >> 5;
    int lane = threadIdx.x & 31;
    if (gwarp >= NNODES) return;

    const float4* xh4 = (const float4*)(g_xh + (size_t)gwarp * DIM);
    float4 v0 = xh4[lane * 2], v1 = xh4[lane * 2 + 1];
    const float4* s4 = (const float4*)a_src;
    const float4* d4 = (const float4*)a_dst;
    float4 s0 = s4[lane * 2], s1 = s4[lane * 2 + 1];
    float4 d0 = d4[lane * 2], d1 = d4[lane * 2 + 1];

    float ps = v0.x * s0.x + v0.y * s0.y + v0.z * s0.z + v0.w * s0.w +
               v1.x * s1.x + v1.y * s1.y + v1.z * s1.z + v1.w * s1.w;
    float pd = v0.x * d0.x + v0.y * d0.y + v0.z * d0.z + v0.w * d0.w +
               v1.x * d1.x + v1.y * d1.y + v1.z * d1.z + v1.w * d1.w;

    ps += __shfl_xor_sync(0xffffffffu, ps, 1);
    ps += __shfl_xor_sync(0xffffffffu, ps, 2);
    pd += __shfl_xor_sync(0xffffffffu, pd, 1);
    pd += __shfl_xor_sync(0xffffffffu, pd, 2);

    if ((lane & 3) == 0) {
        g_als[gwarp * HEADS + (lane >> 2)] = ps;
        g_ald[gwarp * HEADS + (lane >> 2)] = pd;
    }
}

// ---------------- fused online-softmax aggregation (CSR), 2-edge unrolled --------
// one warp per dst node; lane l handles channels [8l,8l+8), head = l>>2
// layers 0-2: writes ELU(out) as bf16 hi/lo splits; layer 3: fp32 to d_out
__global__ void aggr_fused_kernel(const float* __restrict__ bvec,
                                  float* __restrict__ out, int apply_elu) {
    int warp = (blockIdx.x * blockDim.x + threadIdx.x) >> 5;
    int lane = threadIdx.x & 31;
    if (warp >= NNODES) return;

    int beg = g_off[warp], end = g_off[warp + 1];
    int h = lane >> 2;
    float aldh = g_ald[warp * HEADS + h];

    float m = -INFINITY, denom = 0.0f;
    float acc[8];
#pragma unroll
    for (int j = 0; j < 8; j++) acc[j] = 0.0f;

    int i = beg;
    for (; i + 2 <= end; i += 2) {
        int s0 = g_csr_src[i];
        int s1 = g_csr_src[i + 1];
        // issue both gathers + both logit loads before any dependent math (MLP=2)
        const float4* x0 = (const float4*)(g_xh + (size_t)s0 * DIM) + lane * 2;
        const float4* x1 = (const float4*)(g_xh + (size_t)s1 * DIM) + lane * 2;
        float4 u0 = x0[0], u1 = x0[1];
        float4 w0v = x1[0], w1v = x1[1];
        float e0 = g_als[s0 * HEADS + h];
        float e1 = g_als[s1 * HEADS + h];

        e0 += aldh; e0 = e0 > 0.0f ? e0 : 0.2f * e0;
        e1 += aldh; e1 = e1 > 0.0f ? e1 : 0.2f * e1;

        float mn = fmaxf(m, fmaxf(e0, e1));
        float r  = __expf(m - mn);          // m=-inf first time -> r=0
        float a0 = __expf(e0 - mn);
        float a1 = __expf(e1 - mn);
        denom = denom * r + a0 + a1;
        m = mn;

        acc[0] = acc[0] * r + a0 * u0.x + a1 * w0v.x;
        acc[1] = acc[1] * r + a0 * u0.y + a1 * w0v.y;
        acc[2] = acc[2] * r + a0 * u0.z + a1 * w0v.z;
        acc[3] = acc[3] * r + a0 * u0.w + a1 * w0v.w;
        acc[4] = acc[4] * r + a0 * u1.x + a1 * w1v.x;
        acc[5] = acc[5] * r + a0 * u1.y + a1 * w1v.y;
        acc[6] = acc[6] * r + a0 * u1.z + a1 * w1v.z;
        acc[7] = acc[7] * r + a0 * u1.w + a1 * w1v.w;
    }
    if (i < end) {
        int s = g_csr_src[i];
        const float4* xs = (const float4*)(g_xh + (size_t)s * DIM) + lane * 2;
        float4 v0 = xs[0], v1 = xs[1];
        float e = g_als[s * HEADS + h] + aldh;
        e = e > 0.0f ? e : 0.2f * e;
        float mn = fmaxf(m, e);
        float r = __expf(m - mn);
        float a = __expf(e - mn);
        denom = denom * r + a;
        m = mn;
        acc[0] = acc[0] * r + a * v0.x;
        acc[1] = acc[1] * r + a * v0.y;
        acc[2] = acc[2] * r + a * v0.z;
        acc[3] = acc[3] * r + a * v0.w;
        acc[4] = acc[4] * r + a * v1.x;
        acc[5] = acc[5] * r + a * v1.y;
        acc[6] = acc[6] * r + a * v1.z;
        acc[7] = acc[7] * r + a * v1.w;
    }

    float inv = 1.0f / denom;
    const float* bb = bvec + lane * 8;
    float v[8];
#pragma unroll
    for (int j = 0; j < 8; j++) v[j] = acc[j] * inv + bb[j];

    if (apply_elu) {
        __nv_bfloat162 hi2[4], lo2[4];
#pragma unroll
        for (int j = 0; j < 8; j += 2) {
            float v0 = v[j] > 0.0f ? v[j] : expm1f(v[j]);
            float v1 = v[j + 1] > 0.0f ? v[j + 1] : expm1f(v[j + 1]);
            __nv_bfloat16 h0 = __float2bfloat16(v0);
            __nv_bfloat16 h1 = __float2bfloat16(v1);
            hi2[j >> 1] = __halves2bfloat162(h0, h1);
            lo2[j >> 1] = __halves2bfloat162(__float2bfloat16(v0 - __bfloat162float(h0)),
                                             __float2bfloat16(v1 - __bfloat162float(h1)));
        }
        *(uint4*)(g_in_hi + (size_t)warp * DIM + lane * 8) = *(uint4*)hi2;
        *(uint4*)(g_in_lo + (size_t)warp * DIM + lane * 8) = *(uint4*)lo2;
    } else {
        float* o = out + (size_t)warp * DIM + lane * 8;
        *(float4*)(o + 0) = make_float4(v[0], v[1], v[2], v[3]);
        *(float4*)(o + 4) = make_float4(v[4], v[5], v[6], v[7]);
    }
}

// ---------------- host launcher ----------------
extern "C" void kernel_launch(void* const* d_in, const int* in_sizes, int n_in,
                              void* d_out, int out_size) {
    const float* x  = (const float*)d_in[0];
    const int*   ei = (const int*)d_in[1];
    float* out = (float*)d_out;

    cudaFuncSetAttribute(mma_gemm_kernel,
                         cudaFuncAttributeMaxDynamicSharedMemorySize, GEMM_SMEM);

    const int TPB = 256;
    dim3 gemm_grid(DIM / 128, (NNODES + 127) / 128);
    int node_blocks = (NNODES + TPB - 1) / TPB;
    int edge_blocks = (ETOT + TPB - 1) / TPB;
    int warp_blocks = (NNODES * 32 + TPB - 1) / TPB;
    int wsplit_blocks = (DIM * DIM) / TPB;
    int xsplit_blocks = (NNODES * DIM / 4 + TPB - 1) / TPB;

    // build CSR once (same graph for all 4 layers)
    csr_zero_kernel<<<node_blocks, TPB>>>();
    csr_count_kernel<<<edge_blocks, TPB>>>(ei);
    csr_scan_kernel<<<1, 1024>>>();
    csr_scatter_kernel<<<edge_blocks, TPB>>>(ei);

    xsplit_kernel<<<xsplit_blocks, TPB>>>(x);

    for (int layer = 0; layer < 4; layer++) {
        const float* W   = (const float*)d_in[2 + 4 * layer];
        const float* as_ = (const float*)d_in[3 + 4 * layer];
        const float* ad_ = (const float*)d_in[4 + 4 * layer];
        const float* b   = (const float*)d_in[5 + 4 * layer];

        wsplit_kernel<<<wsplit_blocks, TPB>>>(W);
        mma_gemm_kernel<<<gemm_grid, TPB, GEMM_SMEM>>>();
        logits_kernel<<<warp_blocks, TPB>>>(as_, ad_);

        aggr_fused_kernel<<<warp_blocks, TPB>>>(b, (layer < 3) ? nullptr : out,
                                                layer < 3 ? 1 : 0);
    }
}